// round 1
// baseline (speedup 1.0000x reference)
#include <cuda_runtime.h>

#define NN 384
#define TS 32

// Scratch (no device allocation allowed) — u = masked exp(-lam*dist), W = demand/S
__device__ float g_u[NN * NN];
__device__ float g_W[NN * NN];

__device__ __forceinline__ float decode_lam(const void* p) {
    // lambda_param is a python scalar; dtype on device could be int32/int64/float32.
    // Small ints (< 2^24) are never valid float bit patterns of interest here.
    int raw = *(const int*)p;
    unsigned ub = (unsigned)raw;
    if (ub < 0x01000000u) return (float)raw;   // int32 / low word of int64
    return __int_as_float(raw);                // float32 bits
}

// ---------------------------------------------------------------------------
// Kernel 1: u[i,j] = (adj[i,j] > 0 && i != j) ? exp(-lam * dist[i,j]) : 0
// ---------------------------------------------------------------------------
__global__ void k_build_u(const int* __restrict__ adj,
                          const float* __restrict__ dist,
                          const void* __restrict__ lam_p) {
    int idx = blockIdx.x * blockDim.x + threadIdx.x;
    if (idx >= NN * NN) return;
    float lam = decode_lam(lam_p);
    int i = idx / NN;
    int j = idx - i * NN;
    float v = 0.f;
    if (adj[idx] > 0 && i != j) v = expf(-lam * dist[idx]);
    g_u[idx] = v;
}

// ---------------------------------------------------------------------------
// Kernel 2: G = u @ u (row-major NN gemm), fused epilogue:
//   S = u[o,d] + (o!=d ? G : 0);  W = (od>0 && o!=d && S>0) ? od/S : 0
// ---------------------------------------------------------------------------
__global__ __launch_bounds__(1024) void k_G_W(const float* __restrict__ od) {
    __shared__ float As[TS][TS];        // u[row, p]   read As[ty][k] (broadcast)
    __shared__ float Bs[TS][TS];        // u[p, col]   read Bs[k][tx] (stride-1)
    int tx = threadIdx.x, ty = threadIdx.y;
    int row = blockIdx.y * TS + ty;
    int col = blockIdx.x * TS + tx;
    float acc = 0.f;
#pragma unroll 1
    for (int t = 0; t < NN / TS; ++t) {
        int p0 = t * TS;
        As[ty][tx] = g_u[row * NN + p0 + tx];
        Bs[ty][tx] = g_u[(p0 + ty) * NN + col];
        __syncthreads();
#pragma unroll
        for (int k = 0; k < TS; ++k)
            acc = fmaf(As[ty][k], Bs[k][tx], acc);
        __syncthreads();
    }
    int idx = row * NN + col;
    float uod = g_u[idx];
    float S = uod + ((row != col) ? acc : 0.f);
    float odv = od[idx];
    float W = (odv > 0.f && row != col && S > 0.f) ? (odv / S) : 0.f;
    g_W[idx] = W;
}

// ---------------------------------------------------------------------------
// Kernel 3: flows[i,j] = u[i,j] * ( W[i,j]
//                                 + sum_p W[i,p]*u[j,p]      (W · u^T)
//                                 + sum_p u[p,i]*W[p,j] )    (u^T · W)
// Both reductions computed on the same output tile (shared loads of the tile
// index math; total gmem traffic identical to two separate GEMMs but one
// launch and no intermediate store).
// ---------------------------------------------------------------------------
__global__ __launch_bounds__(1024) void k_flows(float* __restrict__ out) {
    __shared__ float Ws[TS][TS];        // W[row, p]          read [ty][k] broadcast
    __shared__ float Ut[TS][TS + 1];    // u[colBlk+j, p]     read [tx][k] -> pad
    __shared__ float Uc[TS][TS];        // u[p, rowBlk+i]     read [k][ty] broadcast
    __shared__ float Wc[TS][TS];        // W[p, colBlk+j]     read [k][tx] stride-1
    int tx = threadIdx.x, ty = threadIdx.y;
    int rowBlk = blockIdx.y * TS;
    int colBlk = blockIdx.x * TS;
    int row = rowBlk + ty;
    int col = colBlk + tx;
    float a1 = 0.f, a2 = 0.f;
#pragma unroll 1
    for (int t = 0; t < NN / TS; ++t) {
        int p0 = t * TS;
        Ws[ty][tx] = g_W[row * NN + p0 + tx];
        Ut[ty][tx] = g_u[(colBlk + ty) * NN + p0 + tx];
        Uc[ty][tx] = g_u[(p0 + ty) * NN + rowBlk + tx];
        Wc[ty][tx] = g_W[(p0 + ty) * NN + colBlk + tx];
        __syncthreads();
#pragma unroll
        for (int k = 0; k < TS; ++k) {
            a1 = fmaf(Ws[ty][k], Ut[tx][k], a1);
            a2 = fmaf(Uc[k][ty], Wc[k][tx], a2);
        }
        __syncthreads();
    }
    int idx = row * NN + col;
    float uv = g_u[idx];
    out[idx] = uv * (g_W[idx] + a1 + a2);
}

// ---------------------------------------------------------------------------
extern "C" void kernel_launch(void* const* d_in, const int* in_sizes, int n_in,
                              void* d_out, int out_size) {
    const float* od   = (const float*)d_in[0];
    const int*   adj  = (const int*)d_in[1];
    const float* dist = (const float*)d_in[2];
    const void*  lamp = d_in[3];
    float* out = (float*)d_out;

    k_build_u<<<(NN * NN + 255) / 256, 256>>>(adj, dist, lamp);

    dim3 blk(TS, TS);
    dim3 grd(NN / TS, NN / TS);
    k_G_W<<<grd, blk>>>(od);
    k_flows<<<grd, blk>>>(out);
}